// round 2
// baseline (speedup 1.0000x reference)
#include <cuda_runtime.h>
#include <math.h>

#define HH 64
#define WW 64
#define BB 2
#define CC 128
#define NH 4
#define DH 32
#define KS 7
#define KK 49
#define NTOK (BB*HH*WW)   // 8192
#define QKV_STRIDE (3*CC) // 384

// scratch (device globals: no allocation allowed)
__device__ float g_qkv[NTOK * 3 * CC];
__device__ float g_att[NTOK * CC];
__device__ float g_y1 [NTOK * CC];
__device__ float g_y2 [NTOK * CC];

// ----------------------------------------------------------------------------
// SGEMM v2: C[M=8192,N] = A @ W^T + bias.  BM=128 BN=64 BK=32, 256 thr, 8x4.
// ----------------------------------------------------------------------------
#define BM 128
#define BN 64
#define BK 32

__global__ void __launch_bounds__(256) sgemm2_kernel(
    const float* __restrict__ A, int a_nchw,
    const float* __restrict__ W,
    const float* __restrict__ bias,
    float* __restrict__ Cout, int N)
{
    __shared__ float sA[BK][132];   // [k][m], padded pitch 132
    __shared__ float sB[BK][68];    // [k][n], padded pitch 68

    const int bm = blockIdx.x * BM;
    const int bn = blockIdx.y * BN;
    const int tid = threadIdx.x;
    const int tx = tid & 15;        // 16 * TN=4 -> 64 cols
    const int ty = tid >> 4;        // 16 * TM=8 -> 128 rows

    float acc[8][4] = {};

    for (int k0 = 0; k0 < CC; k0 += BK) {
        // ---- load A tile ----
        if (a_nchw) {
            // A[t][c] = X[b][c][sp]; whole 128-row tile lies in one batch image
            const int b = bm >> 12;
            const int sp0 = bm & 4095;
            #pragma unroll
            for (int r = 0; r < 4; r++) {
                int k = (tid >> 5) + 8*r;
                int m4 = (tid & 31);
                float4 v = *(const float4*)&A[(b*CC + k0 + k)*4096 + sp0 + m4*4];
                *(float4*)&sA[k][m4*4] = v;   // conflict-free STS.128
            }
        } else {
            #pragma unroll
            for (int r = 0; r < 4; r++) {
                int m  = (tid >> 3) + 32*r;
                int kk = (tid & 7) * 4;
                float4 v = *(const float4*)&A[(bm + m)*CC + k0 + kk];
                sA[kk+0][m] = v.x; sA[kk+1][m] = v.y;
                sA[kk+2][m] = v.z; sA[kk+3][m] = v.w;
            }
        }
        // ---- load W tile: W[n][k], k contiguous ----
        #pragma unroll
        for (int r = 0; r < 2; r++) {
            int n  = (tid >> 3) + 32*r;
            int kk = (tid & 7) * 4;
            float4 v = *(const float4*)&W[(bn + n)*CC + k0 + kk];
            sB[kk+0][n] = v.x; sB[kk+1][n] = v.y;
            sB[kk+2][n] = v.z; sB[kk+3][n] = v.w;
        }
        __syncthreads();

        #pragma unroll
        for (int k = 0; k < BK; k++) {
            float4 a0 = *(const float4*)&sA[k][ty*8];
            float4 a1 = *(const float4*)&sA[k][ty*8 + 4];
            float4 b0 = *(const float4*)&sB[k][tx*4];
            float av[8] = {a0.x,a0.y,a0.z,a0.w,a1.x,a1.y,a1.z,a1.w};
            float bv[4] = {b0.x,b0.y,b0.z,b0.w};
            #pragma unroll
            for (int i = 0; i < 8; i++)
                #pragma unroll
                for (int j = 0; j < 4; j++)
                    acc[i][j] += av[i] * bv[j];
        }
        __syncthreads();
    }

    float4 bb = *(const float4*)&bias[bn + tx*4];
    #pragma unroll
    for (int i = 0; i < 8; i++) {
        int t = bm + ty*8 + i;
        float4 o;
        o.x = acc[i][0] + bb.x; o.y = acc[i][1] + bb.y;
        o.z = acc[i][2] + bb.z; o.w = acc[i][3] + bb.w;
        *(float4*)&Cout[t*N + bn + tx*4] = o;
    }
}

// ----------------------------------------------------------------------------
// Attention v2: 4x4 pixel tile per block; shared 10x10 K/V window in smem.
// 256 threads. Dynamic smem: K(100x132) + V(100x132) + q(16x132) + sc(64x52).
// ----------------------------------------------------------------------------
#define AT 4
#define WR 10
#define WT (WR*WR)   // 100
#define KP 132
#define SCP 52
#define ATTN_SMEM ((WT*KP*2 + 16*KP + 64*SCP) * 4)   // 127360 bytes

__global__ void __launch_bounds__(256) attn2_kernel(
    const float* __restrict__ qkv,
    const float* __restrict__ rpb,   // [NH][13][13]
    float* __restrict__ out)
{
    extern __shared__ float dsm[];
    float* sK = dsm;                 // [WT][KP]
    float* sV = sK + WT*KP;          // [WT][KP]
    float* sq = sV + WT*KP;          // [16][KP]
    float* sc = sq + 16*KP;          // [64][SCP]

    const int blk = blockIdx.x;            // 512 blocks = 2 * 16 * 16
    const int b  = blk >> 8;
    const int ti = (blk >> 4) & 15;
    const int tj = blk & 15;
    const int i0 = ti * AT, j0 = tj * AT;
    const int r0 = min(max(i0 - 3, 0), HH - WR);
    const int c0 = min(max(j0 - 3, 0), WW - WR);
    const int tid = threadIdx.x;

    // ---- phase 1: stage K, V window + scaled q ----
    for (int idx = tid; idx < WT*32; idx += 256) {
        int n  = idx >> 5;
        int c4 = idx & 31;
        int wr = n / WR, wc = n - wr*WR;
        int tt = (b*HH + r0 + wr)*WW + c0 + wc;
        const float4* src = (const float4*)(qkv + (size_t)tt*QKV_STRIDE + CC);
        ((float4*)(sK + n*KP))[c4] = src[c4];
        ((float4*)(sV + n*KP))[c4] = src[c4 + 32];   // V = K base + 128 floats
    }
    for (int idx = tid; idx < 16*32; idx += 256) {
        int p  = idx >> 5;
        int c4 = idx & 31;
        int tt = (b*HH + i0 + (p >> 2))*WW + j0 + (p & 3);
        float4 v = ((const float4*)(qkv + (size_t)tt*QKV_STRIDE))[c4];
        const float sc_q = 0.17677669529663687f;
        v.x *= sc_q; v.y *= sc_q; v.z *= sc_q; v.w *= sc_q;
        ((float4*)(sq + p*KP))[c4] = v;
    }
    __syncthreads();

    // ---- phase 2: scores ----
    {
        const int h = tid >> 6;          // 4
        const int p = (tid >> 2) & 15;   // 16
        const int r = tid & 3;           // 4
        const int pi = p >> 2, pj = p & 3;
        const int i = i0 + pi, j = j0 + pj;
        const int si = min(max(i - 3, 0), HH - KS);
        const int sj = min(max(j - 3, 0), WW - KS);
        const int bro = si - r0, bco = sj - c0;
        const int biasi = 6 - (i - si), biasj = 6 - (j - sj);
        const float* rp = rpb + h*169;

        float4 q[8];
        const float4* qp = (const float4*)(sq + p*KP + h*DH);
        #pragma unroll
        for (int u = 0; u < 8; u++) q[u] = qp[u];

        for (int n = r; n < KK; n += 4) {
            int np = n / 7, nq = n - np*7;
            int wn = (bro + np)*WR + bco + nq;
            const float4* kp = (const float4*)(sK + wn*KP + h*DH);
            float s = 0.f;
            #pragma unroll
            for (int u = 0; u < 8; u++) {
                float4 kv = kp[u];
                s += q[u].x*kv.x + q[u].y*kv.y + q[u].z*kv.z + q[u].w*kv.w;
            }
            s += rp[(np + biasi)*13 + nq + biasj];
            sc[(p*4 + h)*SCP + n] = s;
        }
    }
    __syncthreads();

    // ---- phase 3: softmax per (p,h) row ----
    if (tid < 64) {
        float* row = sc + tid*SCP;
        float m = -1e30f;
        #pragma unroll 7
        for (int n = 0; n < KK; n++) m = fmaxf(m, row[n]);
        float sum = 0.f;
        #pragma unroll 7
        for (int n = 0; n < KK; n++) {
            float e = __expf(row[n] - m);
            row[n] = e; sum += e;
        }
        float inv = 1.f / sum;
        #pragma unroll 7
        for (int n = 0; n < KK; n++) row[n] *= inv;
    }
    __syncthreads();

    // ---- phase 4: AV. warp w handles 8 (p,h) combos; lane = d ----
    {
        const int w = tid >> 5;
        const int lane = tid & 31;
        #pragma unroll
        for (int cc = 0; cc < 8; cc++) {
            int ph = w*8 + cc;
            int p = ph >> 2, h = ph & 3;
            int pi = p >> 2, pj = p & 3;
            int i = i0 + pi, j = j0 + pj;
            int si = min(max(i - 3, 0), HH - KS);
            int sj = min(max(j - 3, 0), WW - KS);
            int bro = si - r0, bco = sj - c0;

            // probs into lane registers, broadcast via shfl (off the crossbar)
            float s0 = sc[ph*SCP + lane];
            float s1 = (lane + 32 < KK) ? sc[ph*SCP + 32 + lane] : 0.f;

            float o = 0.f;
            #pragma unroll
            for (int n = 0; n < KK; n++) {
                float pr = (n < 32) ? __shfl_sync(0xffffffffu, s0, n)
                                    : __shfl_sync(0xffffffffu, s1, n - 32);
                int wn = (bro + n/7)*WR + bco + (n % 7);
                o += pr * sV[wn*KP + h*DH + lane];
            }
            int tt = (b*HH + i)*WW + j;
            out[(size_t)tt*CC + h*DH + lane] = o;
        }
    }
}

// ----------------------------------------------------------------------------
// Final LayerNorm over C + NHWC -> NCHW transpose.
// ----------------------------------------------------------------------------
__global__ void ln_kernel(const float* __restrict__ y,
                          const float* __restrict__ g,
                          const float* __restrict__ bta,
                          float* __restrict__ out)
{
    __shared__ float s[64][133];
    __shared__ float mu[64], rs[64];

    const int row = blockIdx.x;
    const int b = row >> 6, i = row & 63;
    const int base = row * 64 * CC;
    const int tid = threadIdx.x;

    for (int idx = tid; idx < 64*CC; idx += 256) {
        int jj = idx >> 7, c = idx & 127;
        s[jj][c] = y[base + idx];
    }
    __syncthreads();

    if (tid < 64) {
        float sum = 0.f, sq = 0.f;
        #pragma unroll 8
        for (int c = 0; c < CC; c++) {
            float v = s[tid][c];
            sum += v; sq += v*v;
        }
        float m = sum * (1.f/CC);
        mu[tid] = m;
        rs[tid] = rsqrtf(sq * (1.f/CC) - m*m + 1e-5f);
    }
    __syncthreads();

    for (int idx = tid; idx < 64*CC; idx += 256) {
        int c = idx >> 6, jj = idx & 63;
        float v = (s[jj][c] - mu[jj]) * rs[jj] * g[c] + bta[c];
        out[((b*CC + c)*HH + i)*WW + jj] = v;
    }
}

// ----------------------------------------------------------------------------
extern "C" void kernel_launch(void* const* d_in, const int* in_sizes, int n_in,
                              void* d_out, int out_size)
{
    const float* x      = (const float*)d_in[0];
    const float* qkv_w  = (const float*)d_in[1];
    const float* qkv_b  = (const float*)d_in[2];
    const float* rpb    = (const float*)d_in[3];
    const float* proj_w = (const float*)d_in[4];
    const float* proj_b = (const float*)d_in[5];
    const float* ln_g   = (const float*)d_in[6];
    const float* ln_b   = (const float*)d_in[7];
    float* outp = (float*)d_out;

    float *qkvbuf, *attbuf, *y1, *y2;
    cudaGetSymbolAddress((void**)&qkvbuf, g_qkv);
    cudaGetSymbolAddress((void**)&attbuf, g_att);
    cudaGetSymbolAddress((void**)&y1, g_y1);
    cudaGetSymbolAddress((void**)&y2, g_y2);

    static int smem_set = 0;
    if (!smem_set) {
        cudaFuncSetAttribute(attn2_kernel,
                             cudaFuncAttributeMaxDynamicSharedMemorySize,
                             ATTN_SMEM);
        smem_set = 1;
    }

    dim3 gq(NTOK/BM, (3*CC)/BN);   // 64 x 6
    dim3 gp(NTOK/BM, CC/BN);       // 64 x 2
    const int RPB_L = NH*13*13;

    // ---- layer 0 ----
    sgemm2_kernel<<<gq, 256>>>(x, 1, qkv_w, qkv_b, qkvbuf, 3*CC);
    attn2_kernel<<<BB*16*16, 256, ATTN_SMEM>>>(qkvbuf, rpb, attbuf);
    sgemm2_kernel<<<gp, 256>>>(attbuf, 0, proj_w, proj_b, y1, CC);

    // ---- layer 1 ----
    sgemm2_kernel<<<gq, 256>>>(y1, 0, qkv_w + 3*CC*CC, qkv_b + 3*CC, qkvbuf, 3*CC);
    attn2_kernel<<<BB*16*16, 256, ATTN_SMEM>>>(qkvbuf, rpb + RPB_L, attbuf);
    sgemm2_kernel<<<gp, 256>>>(attbuf, 0, proj_w + CC*CC, proj_b + CC, y2, CC);

    // ---- LN + transpose ----
    ln_kernel<<<BB*HH, 256>>>(y2, ln_g, ln_b, outp);
}

// round 3
// speedup vs baseline: 1.6648x; 1.6648x over previous
#include <cuda_runtime.h>
#include <math.h>

#define HH 64
#define WW 64
#define BB 2
#define CC 128
#define NH 4
#define DH 32
#define KS 7
#define KK 49
#define NTOK (BB*HH*WW)   // 8192
#define QKV_STRIDE (3*CC) // 384

// scratch (device globals: no allocation allowed)
__device__ float g_qkv[NTOK * 3 * CC];
__device__ float g_att[NTOK * CC];
__device__ float g_y1 [NTOK * CC];
__device__ float g_y2 [NTOK * CC];

// ----------------------------------------------------------------------------
// SGEMM v3: C[M=8192,N] = A @ W^T + bias.  BM=BN=64, BK=32, 256 thr, 4x4
// microtile with float4 shared loads (2 LDS.128 per 16 FFMA).
// ----------------------------------------------------------------------------
#define BK 32
#define SPITCH 68   // 64 + 4, float4-aligned, stride 4 banks

__global__ void __launch_bounds__(256) sgemm3_kernel(
    const float* __restrict__ A, int a_nchw,
    const float* __restrict__ W,
    const float* __restrict__ bias,
    float* __restrict__ Cout, int N)
{
    __shared__ float sA[BK][SPITCH];   // [k][m]
    __shared__ float sB[BK][SPITCH];   // [k][n]

    const int bm = blockIdx.x * 64;
    const int bn = blockIdx.y * 64;
    const int tid = threadIdx.x;
    const int tx = tid & 15;        // n quad
    const int ty = tid >> 4;        // m quad

    float acc[4][4] = {};

    for (int k0 = 0; k0 < CC; k0 += BK) {
        // ---- A tile: 32k x 64m = 512 float4 ----
        if (a_nchw) {
            const int b = bm >> 12;
            const int sp4 = (bm & 4095) >> 2;
            #pragma unroll
            for (int r = 0; r < 2; r++) {
                int idx = tid + r*256;
                int k = idx >> 4, m4 = idx & 15;
                float4 v = ((const float4*)A)[(b*CC + k0 + k)*1024 + sp4 + m4];
                *(float4*)&sA[k][m4*4] = v;
            }
        } else {
            #pragma unroll
            for (int r = 0; r < 2; r++) {
                int idx = tid + r*256;
                int m = idx >> 3, k4 = idx & 7;
                float4 v = ((const float4*)A)[(bm + m)*32 + (k0 >> 2) + k4];
                sA[k4*4+0][m] = v.x; sA[k4*4+1][m] = v.y;
                sA[k4*4+2][m] = v.z; sA[k4*4+3][m] = v.w;
            }
        }
        // ---- W tile: W[n][k], k contiguous ----
        #pragma unroll
        for (int r = 0; r < 2; r++) {
            int idx = tid + r*256;
            int n = idx >> 3, k4 = idx & 7;
            float4 v = ((const float4*)W)[(bn + n)*32 + (k0 >> 2) + k4];
            sB[k4*4+0][n] = v.x; sB[k4*4+1][n] = v.y;
            sB[k4*4+2][n] = v.z; sB[k4*4+3][n] = v.w;
        }
        __syncthreads();

        #pragma unroll
        for (int k = 0; k < BK; k++) {
            float4 a = *(const float4*)&sA[k][ty*4];
            float4 b = *(const float4*)&sB[k][tx*4];
            float av[4] = {a.x,a.y,a.z,a.w};
            float bv[4] = {b.x,b.y,b.z,b.w};
            #pragma unroll
            for (int i = 0; i < 4; i++)
                #pragma unroll
                for (int j = 0; j < 4; j++)
                    acc[i][j] += av[i] * bv[j];
        }
        __syncthreads();
    }

    float4 bb = *(const float4*)&bias[bn + tx*4];
    #pragma unroll
    for (int i = 0; i < 4; i++) {
        float4 o;
        o.x = acc[i][0] + bb.x; o.y = acc[i][1] + bb.y;
        o.z = acc[i][2] + bb.z; o.w = acc[i][3] + bb.w;
        *(float4*)&Cout[(bm + ty*4 + i)*N + bn + tx*4] = o;
    }
}

// ----------------------------------------------------------------------------
// Attention v3: 2x2 pixel tile per block, 128 threads, warp = head.
// 8x8 K+V window in smem (float4, pitch 132 — conflict-free for both the
// per-lane row reads in QK and the lane-per-d reads in AV).
// ----------------------------------------------------------------------------
#define KP 132
#define ATTN_SMEM ((64*KP*2 + 4*KP + 4*52) * 4)   // 70528 bytes

__global__ void __launch_bounds__(128) attn3_kernel(
    const float* __restrict__ qkv,
    const float* __restrict__ rpb,   // [NH][13][13]
    float* __restrict__ out)
{
    extern __shared__ float dsm[];
    float* sK = dsm;              // [64][KP]
    float* sV = sK + 64*KP;       // [64][KP]
    float* sq = sV + 64*KP;       // [4][KP]
    float* sc = sq + 4*KP;        // [4 heads][52]

    const int blk = blockIdx.x;          // 2048 = 2 * 32 * 32
    const int b  = blk >> 10;
    const int ti = (blk >> 5) & 31;
    const int tj = blk & 31;
    const int i0 = ti*2, j0 = tj*2;
    const int r0 = min(max(i0 - 3, 0), HH - 8);
    const int c0 = min(max(j0 - 3, 0), WW - 8);
    const int tid = threadIdx.x;
    const int h = tid >> 5;
    const int lane = tid & 31;

    // ---- load 8x8 window of K+V (256 contiguous floats per token) ----
    #pragma unroll
    for (int it = 0; it < 32; it++) {
        int idx = tid + it*128;
        int row = idx >> 6, c4 = idx & 63;
        int wr = row >> 3, wc = row & 7;
        int tt = (b*HH + r0 + wr)*WW + c0 + wc;
        float4 v = ((const float4*)qkv)[tt*96 + 32 + c4];
        if (c4 < 32) *(float4*)&sK[row*KP + c4*4] = v;
        else         *(float4*)&sV[row*KP + (c4-32)*4] = v;
    }
    // ---- load 4 q vectors, scaled ----
    {
        int p = tid >> 5, c4 = tid & 31;
        int tt = (b*HH + i0 + (p >> 1))*WW + j0 + (p & 1);
        float4 v = ((const float4*)qkv)[tt*96 + c4];
        const float s = 0.17677669529663687f;   // 32^-0.5
        v.x *= s; v.y *= s; v.z *= s; v.w *= s;
        *(float4*)&sq[p*KP + c4*4] = v;
    }
    __syncthreads();

    const float* rp = rpb + h*169;

    #pragma unroll
    for (int p = 0; p < 4; p++) {
        const int i = i0 + (p >> 1), j = j0 + (p & 1);
        const int si = min(max(i - 3, 0), HH - KS);
        const int sj = min(max(j - 3, 0), WW - KS);
        const int wr0 = si - r0, wc0 = sj - c0;
        const int bi0 = 6 - (i - si), bj0 = 6 - (j - sj);

        // q into registers (broadcast reads)
        float4 q[8];
        const float4* qp = (const float4*)(sq + p*KP + h*DH);
        #pragma unroll
        for (int u = 0; u < 8; u++) q[u] = qp[u];

        // ---- scores: lane -> neighbor (2 rounds: lane, lane+32) ----
        float s0, s1;
        {
            int n = lane;
            int np = n/7, nq = n - np*7;
            const float4* kp = (const float4*)(sK + ((wr0+np)*8 + wc0+nq)*KP + h*DH);
            float ax=0.f, ay=0.f, az=0.f, aw=0.f;
            #pragma unroll
            for (int u = 0; u < 8; u++) {
                float4 kv = kp[u];
                ax += q[u].x*kv.x; ay += q[u].y*kv.y;
                az += q[u].z*kv.z; aw += q[u].w*kv.w;
            }
            s0 = (ax+ay) + (az+aw) + rp[(np+bi0)*13 + nq+bj0];
        }
        const int n2 = lane + 32;
        if (n2 < KK) {
            int np = n2/7, nq = n2 - np*7;
            const float4* kp = (const float4*)(sK + ((wr0+np)*8 + wc0+nq)*KP + h*DH);
            float ax=0.f, ay=0.f, az=0.f, aw=0.f;
            #pragma unroll
            for (int u = 0; u < 8; u++) {
                float4 kv = kp[u];
                ax += q[u].x*kv.x; ay += q[u].y*kv.y;
                az += q[u].z*kv.z; aw += q[u].w*kv.w;
            }
            s1 = (ax+ay) + (az+aw) + rp[(np+bi0)*13 + nq+bj0];
        } else s1 = -1e30f;

        // ---- softmax (warp-resident) ----
        float m = fmaxf(s0, s1);
        #pragma unroll
        for (int o = 16; o > 0; o >>= 1) m = fmaxf(m, __shfl_xor_sync(0xffffffffu, m, o));
        float e0 = __expf(s0 - m);
        float e1 = (n2 < KK) ? __expf(s1 - m) : 0.f;
        float sum = e0 + e1;
        #pragma unroll
        for (int o = 16; o > 0; o >>= 1) sum += __shfl_xor_sync(0xffffffffu, sum, o);
        const float inv = 1.f / sum;

        __syncwarp();
        sc[h*52 + lane] = e0 * inv;
        if (n2 < KK) sc[h*52 + n2] = e1 * inv;
        __syncwarp();

        // ---- AV: lane = d, probs via smem broadcast ----
        float oa = 0.f, ob = 0.f;
        #pragma unroll
        for (int np = 0; np < 7; np++) {
            const float* vrow = sV + ((wr0+np)*8 + wc0)*KP + h*DH + lane;
            const float* prow = sc + h*52 + np*7;
            oa += prow[0]*vrow[0*KP] + prow[2]*vrow[2*KP]
                + prow[4]*vrow[4*KP] + prow[6]*vrow[6*KP];
            ob += prow[1]*vrow[1*KP] + prow[3]*vrow[3*KP]
                + prow[5]*vrow[5*KP];
        }
        int tt = (b*HH + i)*WW + j;
        out[(size_t)tt*CC + h*DH + lane] = oa + ob;
        __syncwarp();
    }
}

// ----------------------------------------------------------------------------
// Final LayerNorm over C + NHWC -> NCHW transpose.
// ----------------------------------------------------------------------------
__global__ void ln_kernel(const float* __restrict__ y,
                          const float* __restrict__ g,
                          const float* __restrict__ bta,
                          float* __restrict__ out)
{
    __shared__ float s[64][133];
    __shared__ float mu[64], rs[64];

    const int row = blockIdx.x;
    const int b = row >> 6, i = row & 63;
    const int base = row * 64 * CC;
    const int tid = threadIdx.x;

    for (int idx = tid; idx < 64*CC; idx += 256) {
        int jj = idx >> 7, c = idx & 127;
        s[jj][c] = y[base + idx];
    }
    __syncthreads();

    if (tid < 64) {
        float sum = 0.f, sq = 0.f;
        #pragma unroll 8
        for (int c = 0; c < CC; c++) {
            float v = s[tid][c];
            sum += v; sq += v*v;
        }
        float m = sum * (1.f/CC);
        mu[tid] = m;
        rs[tid] = rsqrtf(sq * (1.f/CC) - m*m + 1e-5f);
    }
    __syncthreads();

    for (int idx = tid; idx < 64*CC; idx += 256) {
        int c = idx >> 6, jj = idx & 63;
        float v = (s[jj][c] - mu[jj]) * rs[jj] * g[c] + bta[c];
        out[((b*CC + c)*HH + i)*WW + jj] = v;
    }
}

// ----------------------------------------------------------------------------
extern "C" void kernel_launch(void* const* d_in, const int* in_sizes, int n_in,
                              void* d_out, int out_size)
{
    const float* x      = (const float*)d_in[0];
    const float* qkv_w  = (const float*)d_in[1];
    const float* qkv_b  = (const float*)d_in[2];
    const float* rpb    = (const float*)d_in[3];
    const float* proj_w = (const float*)d_in[4];
    const float* proj_b = (const float*)d_in[5];
    const float* ln_g   = (const float*)d_in[6];
    const float* ln_b   = (const float*)d_in[7];
    float* outp = (float*)d_out;

    float *qkvbuf, *attbuf, *y1, *y2;
    cudaGetSymbolAddress((void**)&qkvbuf, g_qkv);
    cudaGetSymbolAddress((void**)&attbuf, g_att);
    cudaGetSymbolAddress((void**)&y1, g_y1);
    cudaGetSymbolAddress((void**)&y2, g_y2);

    static int smem_set = 0;
    if (!smem_set) {
        cudaFuncSetAttribute(attn3_kernel,
                             cudaFuncAttributeMaxDynamicSharedMemorySize,
                             ATTN_SMEM);
        smem_set = 1;
    }

    dim3 gq(NTOK/64, (3*CC)/64);   // 128 x 6
    dim3 gp(NTOK/64, CC/64);       // 128 x 2
    const int RPB_L = NH*13*13;
    const int NATB = BB*32*32;     // 2048

    // ---- layer 0 ----
    sgemm3_kernel<<<gq, 256>>>(x, 1, qkv_w, qkv_b, qkvbuf, 3*CC);
    attn3_kernel<<<NATB, 128, ATTN_SMEM>>>(qkvbuf, rpb, attbuf);
    sgemm3_kernel<<<gp, 256>>>(attbuf, 0, proj_w, proj_b, y1, CC);

    // ---- layer 1 ----
    sgemm3_kernel<<<gq, 256>>>(y1, 0, qkv_w + 3*CC*CC, qkv_b + 3*CC, qkvbuf, 3*CC);
    attn3_kernel<<<NATB, 128, ATTN_SMEM>>>(qkvbuf, rpb + RPB_L, attbuf);
    sgemm3_kernel<<<gp, 256>>>(attbuf, 0, proj_w + CC*CC, proj_b + CC, y2, CC);

    // ---- LN + transpose ----
    ln_kernel<<<BB*HH, 256>>>(y2, ln_g, ln_b, outp);
}